// round 7
// baseline (speedup 1.0000x reference)
#include <cuda_runtime.h>
#include <cuda_bf16.h>
#include <cstdint>

// KVDequantizer: Q4 nibble unpack + per-block (32 elems) scale/bias dequant.
//
// R5: fully async memory pipeline. Per CTA (512 int4 items = 16KB output):
//   TMA bulk load  : packed 8KB + scale 512B + bias 512B  -> SMEM (mbarrier)
//   compute        : LDS -> dequant -> STS (no warp-level global accesses)
//   TMA bulk store : 16KB SMEM -> global
// 8 CTAs/SM pipeline each other's TMA waits; no LDG/STG in the L1tex queue.

static constexpr int TPB       = 256;
static constexpr int ITEMS     = 2;                    // int4 items per thread
static constexpr int CTA_ITEMS = TPB * ITEMS;          // 512 int4 -> 16KB out
static constexpr int NVEC      = 1048576;              // int4 items per tensor
static constexpr int TOTAL     = 2 * NVEC;             // K + V
static constexpr int CTAS      = TOTAL / CTA_ITEMS;    // 4096 (2048 K, 2048 V)
static constexpr int NBLK      = CTA_ITEMS / 4;        // 128 scale blocks per CTA
static constexpr int IN_BYTES  = CTA_ITEMS * 16;       // 8192
static constexpr int SC_BYTES  = NBLK * 4;             // 512
static constexpr int OUT_BYTES = CTA_ITEMS * 32;       // 16384

__device__ __forceinline__ uint32_t smem_u32(const void* p) {
    uint32_t a;
    asm("{ .reg .u64 t; cvta.to.shared.u64 t, %1; cvt.u32.u64 %0, t; }"
        : "=r"(a) : "l"(p));
    return a;
}

__global__ __launch_bounds__(TPB)
void kv_dequant_kernel(const int4* __restrict__ kp,
                       const float* __restrict__ ks,
                       const float* __restrict__ kb,
                       const int4* __restrict__ vp,
                       const float* __restrict__ vs,
                       const float* __restrict__ vb,
                       float* __restrict__ out)
{
    __shared__ __align__(128) int4   s_pack[CTA_ITEMS];       //  8KB
    __shared__ __align__(128) float  s_scale[NBLK];           // 512B
    __shared__ __align__(128) float  s_bias[NBLK];            // 512B
    __shared__ __align__(128) float4 s_out[CTA_ITEMS * 2];    // 16KB
    __shared__ __align__(8)   uint64_t s_mbar;

    const int tid = threadIdx.x;
    const int b   = blockIdx.x;

    // Source pointers for this CTA (first half = K, second half = V).
    const int4*  gp;
    const float* gs;
    const float* gb;
    if (b < CTAS / 2) {
        gp = kp + (long long)b * CTA_ITEMS;
        gs = ks + (long long)b * NBLK;
        gb = kb + (long long)b * NBLK;
    } else {
        int b2 = b - CTAS / 2;
        gp = vp + (long long)b2 * CTA_ITEMS;
        gs = vs + (long long)b2 * NBLK;
        gb = vb + (long long)b2 * NBLK;
    }

    const uint32_t mbar = smem_u32(&s_mbar);

    if (tid == 0) {
        asm volatile("mbarrier.init.shared.b64 [%0], 1;" :: "r"(mbar) : "memory");
    }
    __syncthreads();

    if (tid == 0) {
        asm volatile("mbarrier.arrive.expect_tx.shared.b64 _, [%0], %1;"
                     :: "r"(mbar), "r"(IN_BYTES + 2 * SC_BYTES) : "memory");
        asm volatile("cp.async.bulk.shared::cta.global.mbarrier::complete_tx::bytes "
                     "[%0], [%1], %2, [%3];"
                     :: "r"(smem_u32(s_pack)), "l"(gp), "r"(IN_BYTES), "r"(mbar) : "memory");
        asm volatile("cp.async.bulk.shared::cta.global.mbarrier::complete_tx::bytes "
                     "[%0], [%1], %2, [%3];"
                     :: "r"(smem_u32(s_scale)), "l"(gs), "r"(SC_BYTES), "r"(mbar) : "memory");
        asm volatile("cp.async.bulk.shared::cta.global.mbarrier::complete_tx::bytes "
                     "[%0], [%1], %2, [%3];"
                     :: "r"(smem_u32(s_bias)), "l"(gb), "r"(SC_BYTES), "r"(mbar) : "memory");
    }

    // All threads wait for the loads (phase 0).
    {
        uint32_t done;
        asm volatile(
            "{\n\t"
            ".reg .pred p;\n\t"
            "mbarrier.try_wait.parity.acquire.cta.shared::cta.b64 p, [%1], 0;\n\t"
            "selp.b32 %0, 1, 0, p;\n\t"
            "}" : "=r"(done) : "r"(mbar) : "memory");
        if (!done) {
            asm volatile(
                "{\n\t"
                ".reg .pred P1;\n\t"
                "W_%=:\n\t"
                "mbarrier.try_wait.parity.acquire.cta.shared::cta.b64 P1, [%0], 0, 0x989680;\n\t"
                "@P1 bra.uni D_%=;\n\t"
                "bra.uni W_%=;\n\t"
                "D_%=:\n\t"
                "}" :: "r"(mbar) : "memory");
        }
    }

    // Dequant: items tid and tid+TPB. Low nibble first, then high nibble.
    #pragma unroll
    for (int u = 0; u < ITEMS; u++) {
        int m = tid + u * TPB;                 // item index within CTA
        int4  p = s_pack[m];
        float s = s_scale[m >> 2];
        float bb = s_bias[m >> 2];

        float4 o0, o1;
        o0.x = fmaf((float)(p.x & 15), s, bb);
        o0.y = fmaf((float)(p.x >> 4), s, bb);
        o0.z = fmaf((float)(p.y & 15), s, bb);
        o0.w = fmaf((float)(p.y >> 4), s, bb);
        o1.x = fmaf((float)(p.z & 15), s, bb);
        o1.y = fmaf((float)(p.z >> 4), s, bb);
        o1.z = fmaf((float)(p.w & 15), s, bb);
        o1.w = fmaf((float)(p.w >> 4), s, bb);

        s_out[m * 2]     = o0;
        s_out[m * 2 + 1] = o1;
    }
    __syncthreads();

    // Bulk store: 16KB contiguous. Output offset = global item * 32B, and the
    // V half lands after the K half automatically (b >= CTAS/2).
    if (tid == 0) {
        float* gdst = out + (long long)b * (OUT_BYTES / 4);
        asm volatile("fence.proxy.async.shared::cta;" ::: "memory");
        asm volatile("cp.async.bulk.global.shared::cta.bulk_group [%0], [%1], %2;"
                     :: "l"(gdst), "r"(smem_u32(s_out)), "r"(OUT_BYTES) : "memory");
        asm volatile("cp.async.bulk.commit_group;" ::: "memory");
        asm volatile("cp.async.bulk.wait_group.read 0;" ::: "memory");
    }
}

extern "C" void kernel_launch(void* const* d_in, const int* in_sizes, int n_in,
                              void* d_out, int out_size)
{
    const int4*  kp = (const int4*) d_in[0];
    const float* ks = (const float*)d_in[1];
    const float* kb = (const float*)d_in[2];
    const int4*  vp = (const int4*) d_in[3];
    const float* vs = (const float*)d_in[4];
    const float* vb = (const float*)d_in[5];
    float* out = (float*)d_out;

    kv_dequant_kernel<<<CTAS, TPB>>>(kp, ks, kb, vp, vs, vb, out);
}